// round 17
// baseline (speedup 1.0000x reference)
#include <cuda_runtime.h>
#include <cuda_bf16.h>
#include <cstdint>
#include <math.h>

// NT-Xent contrastive loss, N=4096, D=1024, T=0.5 — bf16 mma.sync, symmetric-half GEMM.
// R16 = R15 (best: 172.8us) with k-chunk doubled to 128 cols: 8 sync points per tile
// instead of 16 (halves CP_WAIT+BAR convoys). Stage = 64KB, 3 stages = 192KB, occ 1
// (occ-1 proven rate-neutral in R3). Epilogue/normalize/final identical to R15.

#define TWO_N 8192
#define NHALF 4096
#define DIM   1024
#define INV_T 2.0f

__device__ __nv_bfloat16 g_zb[(size_t)TWO_N * DIM];
__device__ float g_denom[TWO_N];
__device__ float g_pos[TWO_N];

// ---------------------------------------------------------------- helpers
__device__ __forceinline__ uint32_t smem_u32(const void* p) {
    uint32_t a;
    asm("{ .reg .u64 t; cvta.to.shared.u64 t, %1; cvt.u32.u64 %0, t; }" : "=r"(a) : "l"(p));
    return a;
}

#define CP_ASYNC16(dst, src) \
    asm volatile("cp.async.cg.shared.global [%0], [%1], 16;" :: "r"(dst), "l"(src) : "memory")
#define CP_COMMIT() asm volatile("cp.async.commit_group;" ::: "memory")
#define CP_WAIT(n)  asm volatile("cp.async.wait_group %0;" :: "n"(n) : "memory")

__device__ __forceinline__ void ldsm4(uint32_t* r, uint32_t addr) {
    asm volatile("ldmatrix.sync.aligned.m8n8.x4.shared.b16 {%0,%1,%2,%3}, [%4];"
                 : "=r"(r[0]), "=r"(r[1]), "=r"(r[2]), "=r"(r[3]) : "r"(addr));
}

__device__ __forceinline__ void mma16816(float* c, const uint32_t* a, const uint32_t* b) {
    asm volatile("mma.sync.aligned.m16n8k16.row.col.f32.bf16.bf16.f32 "
                 "{%0,%1,%2,%3}, {%4,%5,%6,%7}, {%8,%9}, {%0,%1,%2,%3};"
                 : "+f"(c[0]), "+f"(c[1]), "+f"(c[2]), "+f"(c[3])
                 : "r"(a[0]), "r"(a[1]), "r"(a[2]), "r"(a[3]), "r"(b[0]), "r"(b[1]));
}

// Stage: A 128x128 bf16 (32KB) + B 128x128 bf16 (32KB).
// Row = 256B = 16 x 16B chunks; swizzle: chunk ch at row r -> ch ^ (r & 7).
#define STAGE_BYTES 65536
#define AS_OFF(s)   ((s) * STAGE_BYTES)
#define BS_OFF(s)   ((s) * STAGE_BYTES + 32768)
#define SMEM_TOTAL  (3 * STAGE_BYTES)

// ---------------------------------------------------------------------------
// Warp-per-row L2-normalize (R15).
// ---------------------------------------------------------------------------
__global__ __launch_bounds__(256) void normalize_kernel(const float* __restrict__ ei,
                                                        const float* __restrict__ ej) {
    const int warp = (blockIdx.x * 256 + threadIdx.x) >> 5;
    const int lane = threadIdx.x & 31;
    const float* src = (warp < NHALF) ? (ei + (size_t)warp * DIM)
                                      : (ej + (size_t)(warp - NHALF) * DIM);
    float4 x[8];
    float s = 0.0f;
#pragma unroll
    for (int i = 0; i < 8; i++) {
        x[i] = ((const float4*)src)[lane + i * 32];
        s += x[i].x * x[i].x + x[i].y * x[i].y + x[i].z * x[i].z + x[i].w * x[i].w;
    }
#pragma unroll
    for (int o = 16; o > 0; o >>= 1) s += __shfl_xor_sync(0xffffffffu, s, o);
    const float inv = 1.0f / fmaxf(sqrtf(s), 1e-12f);

    uint2* dst = (uint2*)(g_zb + (size_t)warp * DIM);
#pragma unroll
    for (int i = 0; i < 8; i++) {
        __nv_bfloat162 a = __floats2bfloat162_rn(x[i].x * inv, x[i].y * inv);
        __nv_bfloat162 b = __floats2bfloat162_rn(x[i].z * inv, x[i].w * inv);
        dst[lane + i * 32] = make_uint2(*(uint32_t*)&a, *(uint32_t*)&b);
    }
    if (lane == 0) g_denom[warp] = 0.0f;
}

// ---------------------------------------------------------------------------
// Symmetric fused GEMM+loss. Tile 128x128, 8 warps (2x4), warp tile 64x32.
// Grid 64x64; CTAs with col-tile < row-tile exit immediately.
// k-chunk = 128 cols (8 chunks of k per tile), 3-stage cp.async pipeline, occ 1.
// ---------------------------------------------------------------------------
__global__ __launch_bounds__(256, 1) void simloss_kernel() {
    const int ti = blockIdx.y;
    const int tj = blockIdx.x;
    if (tj < ti) return;
    const bool diag   = (ti == tj);
    const bool haspos = (tj == ti + 32);
    const int row0 = ti * 128;
    const int col0 = tj * 128;

    extern __shared__ char smem[];
    const uint32_t sb = smem_u32(smem);
    const int tid  = threadIdx.x;
    const int wid  = tid >> 5;
    const int lane = tid & 31;
    const int wm   = wid >> 2;
    const int wn   = wid & 3;

    float acc[4][4][4];
#pragma unroll
    for (int mb = 0; mb < 4; mb++)
#pragma unroll
        for (int nb = 0; nb < 4; nb++)
#pragma unroll
            for (int q = 0; q < 4; q++) acc[mb][nb][q] = 0.0f;

    const int a_row = lane & 15;
    const int a_sel = lane >> 4;
    const int b_n   = (lane & 7) + ((lane >> 4) << 3);
    const int b_sel = (lane >> 3) & 1;

    // Stage holds 128 rows x 256B for A and B: 2048 16B-chunks each.
    auto load_stage = [&](int s, int kc) {
        const size_t k0 = (size_t)kc * 128;
#pragma unroll
        for (int i = 0; i < 16; i++) {
            const int idx = tid + i * 256;
            if (idx < 2048) {
                const int r = idx >> 4, ch = idx & 15;
                CP_ASYNC16(sb + AS_OFF(s) + r * 256 + ((ch ^ (r & 7)) << 4),
                           g_zb + (size_t)(row0 + r) * DIM + k0 + ch * 8);
            } else if (!diag) {
                const int j = idx - 2048;
                const int r = j >> 4, ch = j & 15;
                CP_ASYNC16(sb + BS_OFF(s) + r * 256 + ((ch ^ (r & 7)) << 4),
                           g_zb + (size_t)(col0 + r) * DIM + k0 + ch * 8);
            }
        }
    };

    auto compute_stage = [&](int s) {
        const uint32_t as = sb + AS_OFF(s);
        const uint32_t bs = diag ? as : (sb + BS_OFF(s));
#pragma unroll
        for (int kk = 0; kk < 8; kk++) {       // 8 x k16 per 256B row
            uint32_t a[4][4], b[2][4];
#pragma unroll
            for (int mb = 0; mb < 4; mb++) {
                const int r = wm * 64 + mb * 16 + a_row;
                const int ch = kk * 2 + a_sel;
                ldsm4(a[mb], as + r * 256 + ((ch ^ (r & 7)) << 4));
            }
#pragma unroll
            for (int nb2 = 0; nb2 < 2; nb2++) {
                const int r = wn * 32 + nb2 * 16 + b_n;
                const int ch = kk * 2 + b_sel;
                ldsm4(b[nb2], bs + r * 256 + ((ch ^ (r & 7)) << 4));
            }
#pragma unroll
            for (int mb = 0; mb < 4; mb++)
#pragma unroll
                for (int nb = 0; nb < 4; nb++)
                    mma16816(acc[mb][nb], a[mb], &b[nb >> 1][(nb & 1) * 2]);
        }
    };

    load_stage(0, 0); CP_COMMIT();
    load_stage(1, 1); CP_COMMIT();
    CP_WAIT(1);
    __syncthreads();

    for (int ks = 0; ks < 8; ks++) {
        compute_stage(ks % 3);
        if (ks + 2 < 8) {
            load_stage((ks + 2) % 3, ks + 2);
            CP_COMMIT();
            CP_WAIT(1);
            __syncthreads();
        } else if (ks + 1 < 8) {
            CP_WAIT(0);
            __syncthreads();
        }
    }

    // ---------------- epilogue: direct global reduction (no smem) ----------------
    float colacc[4][2];
#pragma unroll
    for (int nb = 0; nb < 4; nb++) colacc[nb][0] = colacc[nb][1] = 0.0f;

#pragma unroll
    for (int mb = 0; mb < 4; mb++) {
        const int lrow = wm * 64 + mb * 16 + (lane >> 2);
        const int r_lo = row0 + lrow;
        const int r_hi = r_lo + 8;
        float slo = 0.0f, shi = 0.0f;
#pragma unroll
        for (int nb = 0; nb < 4; nb++) {
            const int c = col0 + wn * 32 + nb * 8 + (lane & 3) * 2;
            const float v0 = acc[mb][nb][0], v1 = acc[mb][nb][1];
            const float v2 = acc[mb][nb][2], v3 = acc[mb][nb][3];
            float e0 = __expf(v0 * INV_T), e1 = __expf(v1 * INV_T);
            float e2 = __expf(v2 * INV_T), e3 = __expf(v3 * INV_T);
            if (diag) {
                if (c     == r_lo) e0 = 0.0f;
                if (c + 1 == r_lo) e1 = 0.0f;
                if (c     == r_hi) e2 = 0.0f;
                if (c + 1 == r_hi) e3 = 0.0f;
            }
            if (haspos) {
                const int p_lo = r_lo + NHALF;
                const int p_hi = r_hi + NHALF;
                if (c     == p_lo) { g_pos[r_lo] = v0; g_pos[c]     = v0; }
                if (c + 1 == p_lo) { g_pos[r_lo] = v1; g_pos[c + 1] = v1; }
                if (c     == p_hi) { g_pos[r_hi] = v2; g_pos[c]     = v2; }
                if (c + 1 == p_hi) { g_pos[r_hi] = v3; g_pos[c + 1] = v3; }
            }
            slo += e0 + e1;  shi += e2 + e3;
            colacc[nb][0] += e0 + e2;
            colacc[nb][1] += e1 + e3;
        }
        slo += __shfl_xor_sync(0xffffffffu, slo, 1);
        slo += __shfl_xor_sync(0xffffffffu, slo, 2);
        shi += __shfl_xor_sync(0xffffffffu, shi, 1);
        shi += __shfl_xor_sync(0xffffffffu, shi, 2);
        if ((lane & 3) == 0) {
            atomicAdd(&g_denom[r_lo], slo);
            atomicAdd(&g_denom[r_hi], shi);
        }
    }

    if (!diag) {
#pragma unroll
        for (int nb = 0; nb < 4; nb++) {
#pragma unroll
            for (int p = 0; p < 2; p++) {
                float cs = colacc[nb][p];
                cs += __shfl_xor_sync(0xffffffffu, cs, 4);
                cs += __shfl_xor_sync(0xffffffffu, cs, 8);
                cs += __shfl_xor_sync(0xffffffffu, cs, 16);
                if ((lane >> 2) == 0)
                    atomicAdd(&g_denom[col0 + wn * 32 + nb * 8 + (lane & 3) * 2 + p], cs);
            }
        }
    }
}

// ---------------------------------------------------------------------------
// Single-block final reduction (separate launch).
// ---------------------------------------------------------------------------
__global__ __launch_bounds__(1024) void loss_final_kernel(float* __restrict__ out) {
    const int t = threadIdx.x;
    float v = 0.0f;
#pragma unroll
    for (int i = 0; i < 8; i++) {
        const int r = t + i * 1024;
        v += logf(g_denom[r]) - g_pos[r] * INV_T;
    }
#pragma unroll
    for (int o = 16; o > 0; o >>= 1) v += __shfl_xor_sync(0xffffffffu, v, o);
    __shared__ float ws[32];
    if ((t & 31) == 0) ws[t >> 5] = v;
    __syncthreads();
    if (t < 32) {
        float s = ws[t];
#pragma unroll
        for (int o = 16; o > 0; o >>= 1) s += __shfl_xor_sync(0xffffffffu, s, o);
        if (t == 0) out[0] = s * (1.0f / (float)TWO_N);
    }
}

// ---------------------------------------------------------------------------
extern "C" void kernel_launch(void* const* d_in, const int* in_sizes, int n_in,
                              void* d_out, int out_size) {
    const float* emb_i = (const float*)d_in[0];
    const float* emb_j = (const float*)d_in[1];
    float* out = (float*)d_out;

    cudaFuncSetAttribute(simloss_kernel, cudaFuncAttributeMaxDynamicSharedMemorySize,
                         SMEM_TOTAL);

    normalize_kernel<<<TWO_N / 8, 256>>>(emb_i, emb_j);
    dim3 grid(64, 64);
    simloss_kernel<<<grid, 256, SMEM_TOTAL>>>();
    loss_final_kernel<<<1, 1024>>>(out);
}